// round 8
// baseline (speedup 1.0000x reference)
#include <cuda_runtime.h>
#include <cuda_bf16.h>
#include <math.h>

typedef __nv_bfloat16 bf16;

#define NB 4
#define S 2048
#define DM 1024
#define NH 16
#define DP 64
#define DFF 4096
#define MT (NB*S)      // 8192
#define BH (NB*NH)     // 64
#define EPS 1e-6f

// ---------------- static scratch (~0.63 GB total) ----------------
__device__ float g_q[MT*DM];
__device__ float g_k[MT*DM];
__device__ float g_v[MT*DM];
__device__ float g_ctx[MT*DM];
__device__ float g_out1[MT*DM];
__device__ float g_out2[MT*DM];
__device__ float g_tmp[MT*DM];
__device__ float g_ffn[(size_t)MT*DFF];         // 128MB
__device__ bf16  g_ab[(size_t)MT*2*DFF];        // 128MB: [Ah|Al] activations
__device__ bf16  g_wt[(size_t)DFF*2*DM];        // 16MB:  [Bh|Bl] weights^T
__device__ bf16  g_qs[(size_t)BH*S*128];        // 32MB: Q per head [hi64|lo64]
__device__ bf16  g_ks[(size_t)BH*S*128];        // 32MB: K per head [hi64|lo64]
__device__ bf16  g_vs[(size_t)BH*DP*2*S];       // 32MB: V^T per head [hi|lo]

// ---------------- helpers ----------------
__device__ __forceinline__ unsigned bpack(bf16 a, bf16 b) {
    unsigned short ua = *reinterpret_cast<unsigned short*>(&a);
    unsigned short ub = *reinterpret_cast<unsigned short*>(&b);
    return (unsigned)ua | ((unsigned)ub << 16);
}
__device__ __forceinline__ void split1(float x, bf16& h, bf16& l) {
    h = __float2bfloat16_rn(x);
    l = __float2bfloat16_rn(x - __bfloat162float(h));
}
__device__ __forceinline__ void cp16(void* smem, const void* g) {
    unsigned s = (unsigned)__cvta_generic_to_shared(smem);
    asm volatile("cp.async.cg.shared.global [%0], [%1], 16;\n" :: "r"(s), "l"(g));
}
#define CP_COMMIT asm volatile("cp.async.commit_group;\n" ::)
#define CP_WAIT0  asm volatile("cp.async.wait_group 0;\n" ::)

__device__ __forceinline__ void mma16816(float* c, const unsigned* a, const unsigned* b) {
    asm volatile(
        "mma.sync.aligned.m16n8k16.row.col.f32.bf16.bf16.f32 "
        "{%0,%1,%2,%3}, {%4,%5,%6,%7}, {%8,%9}, {%0,%1,%2,%3};\n"
        : "+f"(c[0]), "+f"(c[1]), "+f"(c[2]), "+f"(c[3])
        : "r"(a[0]), "r"(a[1]), "r"(a[2]), "r"(a[3]), "r"(b[0]), "r"(b[1]));
}

// plain single-term warp mma over a 32-wide k-chunk (used by flash)
template<int MI, int NI, int LD>
__device__ __forceinline__ void wmma_ks(const bf16* As, const bf16* Bs, int lane,
                                        float acc[MI][NI][4])
{
    const int g = lane >> 2, t2 = (lane & 3) << 1;
    #pragma unroll
    for (int ks = 0; ks < 32; ks += 16) {
        unsigned a[MI][4], bb[NI][2];
        #pragma unroll
        for (int mi = 0; mi < MI; mi++) {
            const bf16* p = As + (mi*16 + g) * LD + ks + t2;
            a[mi][0] = *(const unsigned*)p;
            a[mi][1] = *(const unsigned*)(p + 8*LD);
            a[mi][2] = *(const unsigned*)(p + 8);
            a[mi][3] = *(const unsigned*)(p + 8*LD + 8);
        }
        #pragma unroll
        for (int ni = 0; ni < NI; ni++) {
            const bf16* p = Bs + (ni*8 + g) * LD + ks + t2;
            bb[ni][0] = *(const unsigned*)p;
            bb[ni][1] = *(const unsigned*)(p + 8);
        }
        #pragma unroll
        for (int mi = 0; mi < MI; mi++)
            #pragma unroll
            for (int ni = 0; ni < NI; ni++)
                mma16816(acc[mi][ni], a[mi], bb[ni]);
    }
}

// 3-term Markidis warp mma on ONE k16 chunk; smem rows: [hi16 | lo16 | pad8]
// acc += Ah.Bh + Ah.Bl + Al.Bh
template<int MI, int NI, int LD>
__device__ __forceinline__ void wmma3_16(const bf16* As, const bf16* Bs, int lane,
                                         float acc[MI][NI][4])
{
    const int g = lane >> 2, t2 = (lane & 3) << 1;
    unsigned ah[MI][4], al[MI][4], bh_[NI][2], bl_[NI][2];
    #pragma unroll
    for (int mi = 0; mi < MI; mi++) {
        const bf16* p = As + (mi*16 + g) * LD + t2;
        ah[mi][0] = *(const unsigned*)p;
        ah[mi][1] = *(const unsigned*)(p + 8*LD);
        ah[mi][2] = *(const unsigned*)(p + 8);
        ah[mi][3] = *(const unsigned*)(p + 8*LD + 8);
        al[mi][0] = *(const unsigned*)(p + 16);
        al[mi][1] = *(const unsigned*)(p + 8*LD + 16);
        al[mi][2] = *(const unsigned*)(p + 24);
        al[mi][3] = *(const unsigned*)(p + 8*LD + 24);
    }
    #pragma unroll
    for (int ni = 0; ni < NI; ni++) {
        const bf16* p = Bs + (ni*8 + g) * LD + t2;
        bh_[ni][0] = *(const unsigned*)p;
        bh_[ni][1] = *(const unsigned*)(p + 8);
        bl_[ni][0] = *(const unsigned*)(p + 16);
        bl_[ni][1] = *(const unsigned*)(p + 24);
    }
    #pragma unroll
    for (int mi = 0; mi < MI; mi++)
        #pragma unroll
        for (int ni = 0; ni < NI; ni++) {
            mma16816(acc[mi][ni], ah[mi], bh_[ni]);
            mma16816(acc[mi][ni], ah[mi], bl_[ni]);
            mma16816(acc[mi][ni], al[mi], bh_[ni]);
        }
}

// ---------------- conversion kernels ----------------
// fp32 [M,K] -> bf16 [M,2K] = [hi | lo]
__global__ __launch_bounds__(256) void split_rows(
    const float* __restrict__ in, bf16* __restrict__ out, int K)
{
    int id = blockIdx.x * 256 + threadIdx.x;
    int kq = K >> 2;
    int row = id / kq, c4 = id - row * kq;
    float4 v = ((const float4*)in)[(size_t)row * kq + c4];
    bf16 h0,h1,h2,h3,l0,l1,l2,l3;
    split1(v.x,h0,l0); split1(v.y,h1,l1); split1(v.z,h2,l2); split1(v.w,h3,l3);
    uint2 hp = {bpack(h0,h1), bpack(h2,h3)};
    uint2 lp = {bpack(l0,l1), bpack(l2,l3)};
    size_t base = (size_t)row * 2 * K + c4 * 4;
    *(uint2*)(out + base)     = hp;
    *(uint2*)(out + base + K) = lp;
}

// fp32 W[K,N] -> bf16 Wt[N,2K] = [hi | lo]  (transposed)
__global__ void split_wt(const float* __restrict__ W, bf16* __restrict__ Wt,
                         int K, int N)
{
    __shared__ float t[32][33];
    int k0 = blockIdx.y * 32, n0 = blockIdx.x * 32;
    int tx = threadIdx.x, ty = threadIdx.y;
    #pragma unroll
    for (int j = 0; j < 4; j++)
        t[ty + j*8][tx] = W[(size_t)(k0 + ty + j*8) * N + n0 + tx];
    __syncthreads();
    int K2 = 2 * K;
    #pragma unroll
    for (int j = 0; j < 4; j++) {
        int n = n0 + ty + j*8, k = k0 + tx;
        bf16 h, l; split1(t[tx][ty + j*8], h, l);
        Wt[(size_t)n*K2 + k]     = h;
        Wt[(size_t)n*K2 + K + k] = l;
    }
}

// fp32 [b*S+q][h*64+d] -> bf16 [bh][q][128] = [hi64 | lo64]
__global__ __launch_bounds__(256) void split_qk(
    const float* __restrict__ in, bf16* __restrict__ out)
{
    int id = blockIdx.x * 256 + threadIdx.x;
    int row = id >> 8, c4 = id & 255;
    float4 v = ((const float4*)in)[(size_t)row * 256 + c4];
    int col = c4 * 4, h = col >> 6, d = col & 63;
    int b = row >> 11, q = row & 2047;
    bf16 h0,h1,h2,h3,l0,l1,l2,l3;
    split1(v.x,h0,l0); split1(v.y,h1,l1); split1(v.z,h2,l2); split1(v.w,h3,l3);
    uint2 hp = {bpack(h0,h1), bpack(h2,h3)};
    uint2 lp = {bpack(l0,l1), bpack(l2,l3)};
    size_t base = ((size_t)((b*NH + h)*S + q)) * 128 + d;
    *(uint2*)(out + base)      = hp;
    *(uint2*)(out + base + 64) = lp;
}

// fp32 V [b*S+k][h*64+d] -> bf16 Vs[bh][d][2S] = [hi | lo]
__global__ void split_v(const float* __restrict__ v, bf16* __restrict__ vs)
{
    __shared__ float t[32][33];
    int k0 = blockIdx.x * 32, d0 = blockIdx.y * 32, bh = blockIdx.z;
    int b = bh >> 4, h = bh & 15;
    int tx = threadIdx.x, ty = threadIdx.y;
    #pragma unroll
    for (int j = 0; j < 4; j++)
        t[ty + j*8][tx] = v[(size_t)(b*S + k0 + ty + j*8)*DM + h*64 + d0 + tx];
    __syncthreads();
    #pragma unroll
    for (int j = 0; j < 4; j++) {
        int d = d0 + ty + j*8, k = k0 + tx;
        bf16 hi, lo; split1(t[tx][ty + j*8], hi, lo);
        size_t base = ((size_t)bh*64 + d) * (2*S) + k;
        vs[base]     = hi;
        vs[base + S] = lo;
    }
}

// ---------------- dense GEMM: C[M,N] = (Ah+Al).(Bh+Bl)^T (3 terms) + bias --
// A [M,2K]=[Ah|Al], Bt [N,2K]=[Bh|Bl].
// Static smem, k16 chunks, rows [hi16|lo16|pad8] (stride 40), double-buffered.
__global__ __launch_bounds__(256) void hgemm_bias(
    const bf16* __restrict__ A, const bf16* __restrict__ Bt,
    const float* __restrict__ bias, float* __restrict__ C,
    int Nd, int K, int relu)
{
    __shared__ bf16 As[2][128*40];
    __shared__ bf16 Bs[2][128*40];
    const int tid = threadIdx.x, lane = tid & 31, warp = tid >> 5;
    const int wm = warp >> 2, wn = warp & 3;
    const int m0 = blockIdx.y * 128, n0 = blockIdx.x * 128;
    const int K2 = 2 * K;
    const bf16* Ag = A  + (size_t)m0 * K2;
    const bf16* Bg = Bt + (size_t)n0 * K2;
    float acc[4][4][4] = {};
    const int KT = K >> 4;

    const int r = tid >> 1;                 // 0..127
    const int half = tid & 1;               // 0=hi, 1=lo
    const int so = r*40 + half*16;          // smem row offset
    const size_t go = (size_t)r*K2 + (size_t)half*K;

    // prologue chunk 0
    cp16(&As[0][so],     Ag + go);
    cp16(&As[0][so + 8], Ag + go + 8);
    cp16(&Bs[0][so],     Bg + go);
    cp16(&Bs[0][so + 8], Bg + go + 8);
    CP_COMMIT;

    for (int kt = 0; kt < KT; kt++) {
        CP_WAIT0; __syncthreads();
        if (kt + 1 < KT) {
            const int st = (kt + 1) & 1;
            const int kp = (kt + 1) * 16;
            cp16(&As[st][so],     Ag + go + kp);
            cp16(&As[st][so + 8], Ag + go + kp + 8);
            cp16(&Bs[st][so],     Bg + go + kp);
            cp16(&Bs[st][so + 8], Bg + go + kp + 8);
            CP_COMMIT;
        }
        wmma3_16<4,4,40>(&As[kt&1][wm*64*40], &Bs[kt&1][wn*32*40], lane, acc);
        __syncthreads();
    }

    const int g = lane >> 2, t2 = (lane & 3) << 1;
    #pragma unroll
    for (int mi = 0; mi < 4; mi++)
        #pragma unroll
        for (int ni = 0; ni < 4; ni++) {
            const int rr = m0 + wm*64 + mi*16 + g;
            const int c = n0 + wn*32 + ni*8 + t2;
            float2 bv = *(const float2*)(bias + c);
            float2 o1 = {acc[mi][ni][0] + bv.x, acc[mi][ni][1] + bv.y};
            float2 o2 = {acc[mi][ni][2] + bv.x, acc[mi][ni][3] + bv.y};
            if (relu) {
                o1.x = fmaxf(o1.x, 0.f); o1.y = fmaxf(o1.y, 0.f);
                o2.x = fmaxf(o2.x, 0.f); o2.y = fmaxf(o2.y, 0.f);
            }
            *(float2*)(C + (size_t)rr*Nd + c)      = o1;
            *(float2*)(C + (size_t)(rr+8)*Nd + c)  = o2;
        }
}

// ---------------- fused flash attention ------------------------------------
// Q/K rows [hi64|lo64]; V^T rows [hi(S)|lo(S)].
// scores = Qh.Kh + Qh.Kl + Ql.Kh ; PV = Ph.Vh + Ph.Vl + Pl.Vh
template<int MODE>
__global__ __launch_bounds__(256, 2) void flash_attn(
    const bf16* __restrict__ Qg, const bf16* __restrict__ Kg,
    const bf16* __restrict__ Vg, const float* __restrict__ mask,
    float* __restrict__ lg, float* __restrict__ ctx)
{
    extern __shared__ bf16 sm[];
    bf16* Qs = sm;                      // [128][136]
    bf16* Ks = sm + 128*136;            // [64][136]
    bf16* Vt = sm + 128*136 + 64*136;   // [64][136]: hi cols 0-63, lo 64-127

    const int tid = threadIdx.x, lane = tid & 31, warp = tid >> 5;
    const int g = lane >> 2, t2 = (lane & 3) << 1;
    const int bh = blockIdx.y, b = bh >> 4, h = bh & 15;
    const int q0 = blockIdx.x * 128;
    const int qr = q0 + warp*16 + g;

    // load Q tile once: 128 x 128
    {
        const bf16* src = Qg + ((size_t)bh*S + q0) * 128;
        const int rq = tid >> 1, hf = (tid & 1) * 64;
        #pragma unroll
        for (int i = 0; i < 8; i++)
            cp16(Qs + rq*136 + hf + i*8, src + (size_t)rq*128 + hf + i*8);
    }
    CP_COMMIT; CP_WAIT0; __syncthreads();

    float m_lo = -INFINITY, m_hi = -INFINITY, l_lo = 0.f, l_hi = 0.f;
    float acc_o[8][4] = {};

    for (int k0 = 0; k0 < S; k0 += 64) {
        __syncthreads();
        // K chunk 64 x 128
        {
            const int rk = tid >> 2, qt = (tid & 3) * 32;
            const bf16* src = Kg + ((size_t)bh*S + k0 + rk) * 128;
            #pragma unroll
            for (int i = 0; i < 4; i++)
                cp16(Ks + rk*136 + qt + i*8, src + qt + i*8);
        }
        // V chunk
        {
            const int d = tid >> 2;
            const bf16* vb = Vg + ((size_t)bh*64 + d) * (2*S);
            #pragma unroll
            for (int i = 0; i < 4; i++) {
                const int j = (tid & 3) + i*4;                // 0..15
                const int src = (j < 8) ? (k0 + j*8) : (S + k0 + (j-8)*8);
                cp16(Vt + d*136 + j*8, vb + src);
            }
        }
        CP_COMMIT; CP_WAIT0; __syncthreads();

        // scores 128x64 (3 Markidis terms)
        float sacc[1][8][4] = {};
        #pragma unroll
        for (int t = 0; t < 3; t++) {
            const int qo = (t == 2) ? 64 : 0;
            const int ko = (t == 1) ? 64 : 0;
            #pragma unroll
            for (int kc = 0; kc < 64; kc += 32)
                wmma_ks<1,8,136>(Qs + (warp*16)*136 + qo + kc,
                                 Ks + ko + kc, lane, sacc);
        }

        // scale + mask (+ logits out), tile max
        float mt_lo = -INFINITY, mt_hi = -INFINITY;
        #pragma unroll
        for (int ni = 0; ni < 8; ni++) {
            const int kk = k0 + ni*8 + t2;
            float2 mA, mB;
            if (MODE == 0) {
                mA = *(const float2*)(mask + ((size_t)b*S + qr)*S + kk);
                mB = *(const float2*)(mask + ((size_t)b*S + qr + 8)*S + kk);
            } else {
                mA = *(const float2*)(mask + (size_t)b*S + kk);
                mB = mA;
            }
            sacc[0][ni][0] = sacc[0][ni][0]*0.125f + mA.x*(-1e9f);
            sacc[0][ni][1] = sacc[0][ni][1]*0.125f + mA.y*(-1e9f);
            sacc[0][ni][2] = sacc[0][ni][2]*0.125f + mB.x*(-1e9f);
            sacc[0][ni][3] = sacc[0][ni][3]*0.125f + mB.y*(-1e9f);
            if (MODE == 1) {
                *(float2*)(lg + ((size_t)bh*S + qr)*S + kk) =
                    make_float2(sacc[0][ni][0], sacc[0][ni][1]);
                *(float2*)(lg + ((size_t)bh*S + qr + 8)*S + kk) =
                    make_float2(sacc[0][ni][2], sacc[0][ni][3]);
            }
            mt_lo = fmaxf(mt_lo, fmaxf(sacc[0][ni][0], sacc[0][ni][1]));
            mt_hi = fmaxf(mt_hi, fmaxf(sacc[0][ni][2], sacc[0][ni][3]));
        }
        #pragma unroll
        for (int off = 1; off <= 2; off <<= 1) {
            mt_lo = fmaxf(mt_lo, __shfl_xor_sync(~0u, mt_lo, off));
            mt_hi = fmaxf(mt_hi, __shfl_xor_sync(~0u, mt_hi, off));
        }
        const float mn_lo = fmaxf(m_lo, mt_lo), mn_hi = fmaxf(m_hi, mt_hi);
        const float al_lo = __expf(m_lo - mn_lo), al_hi = __expf(m_hi - mn_hi);
        m_lo = mn_lo; m_hi = mn_hi;

        // p = exp(s - m), build P fragments (hi & lo), row sums
        unsigned pa_h[4][4], pa_l[4][4];
        float rs_lo = 0.f, rs_hi = 0.f;
        #pragma unroll
        for (int ni = 0; ni < 8; ni++) {
            float p0 = __expf(sacc[0][ni][0] - mn_lo);
            float p1 = __expf(sacc[0][ni][1] - mn_lo);
            float p2 = __expf(sacc[0][ni][2] - mn_hi);
            float p3 = __expf(sacc[0][ni][3] - mn_hi);
            rs_lo += p0 + p1; rs_hi += p2 + p3;
            bf16 h0,l0,h1,l1,h2,l2,h3,l3;
            split1(p0,h0,l0); split1(p1,h1,l1); split1(p2,h2,l2); split1(p3,h3,l3);
            const int j = ni >> 1;
            if ((ni & 1) == 0) {
                pa_h[j][0] = bpack(h0,h1); pa_h[j][1] = bpack(h2,h3);
                pa_l[j][0] = bpack(l0,l1); pa_l[j][1] = bpack(l2,l3);
            } else {
                pa_h[j][2] = bpack(h0,h1); pa_h[j][3] = bpack(h2,h3);
                pa_l[j][2] = bpack(l0,l1); pa_l[j][3] = bpack(l2,l3);
            }
        }
        #pragma unroll
        for (int off = 1; off <= 2; off <<= 1) {
            rs_lo += __shfl_xor_sync(~0u, rs_lo, off);
            rs_hi += __shfl_xor_sync(~0u, rs_hi, off);
        }
        l_lo = l_lo*al_lo + rs_lo; l_hi = l_hi*al_hi + rs_hi;

        #pragma unroll
        for (int nd = 0; nd < 8; nd++) {
            acc_o[nd][0] *= al_lo; acc_o[nd][1] *= al_lo;
            acc_o[nd][2] *= al_hi; acc_o[nd][3] *= al_hi;
        }
        // PV: 3 terms, shared fragments
        #pragma unroll
        for (int j = 0; j < 4; j++)
            #pragma unroll
            for (int nd = 0; nd < 8; nd++) {
                const bf16* pv = Vt + (nd*8 + g)*136 + j*16 + t2;
                unsigned bh2[2], bl2[2];
                bh2[0] = *(const unsigned*)pv;        bh2[1] = *(const unsigned*)(pv + 8);
                bl2[0] = *(const unsigned*)(pv + 64); bl2[1] = *(const unsigned*)(pv + 72);
                mma16816(acc_o[nd], pa_h[j], bh2);
                mma16816(acc_o[nd], pa_l[j], bh2);
                mma16816(acc_o[nd], pa_h[j], bl2);
            }
    }

    const float il_lo = 1.f / l_lo, il_hi = 1.f / l_hi;
    #pragma unroll
    for (int nd = 0; nd < 8; nd++) {
        const int d = nd*8 + t2;
        size_t base = ((size_t)b*S + qr)*DM + h*64 + d;
        *(float2*)(ctx + base)        = make_float2(acc_o[nd][0]*il_lo, acc_o[nd][1]*il_lo);
        *(float2*)(ctx + base + 8*DM) = make_float2(acc_o[nd][2]*il_hi, acc_o[nd][3]*il_hi);
    }
}

// ---------------- fused residual add + LayerNorm --------------------------
__global__ __launch_bounds__(256) void add_ln_kernel(
    const float* __restrict__ a, const float* __restrict__ bres,
    const float* __restrict__ g, const float* __restrict__ beta,
    float* __restrict__ out)
{
    const size_t row = blockIdx.x;
    const float* pa = a + row * DM;
    const float* pb = bres + row * DM;
    const int tid = threadIdx.x, lane = tid & 31, warp = tid >> 5;
    __shared__ float rs1[8], rs2[8];

    float x[4];
    float s = 0.f, s2 = 0.f;
    #pragma unroll
    for (int i = 0; i < 4; i++) {
        float t = pa[tid + i*256] + pb[tid + i*256];
        x[i] = t; s += t; s2 += t * t;
    }
    #pragma unroll
    for (int off = 16; off; off >>= 1) {
        s  += __shfl_xor_sync(~0u, s, off);
        s2 += __shfl_xor_sync(~0u, s2, off);
    }
    if (lane == 0) { rs1[warp] = s; rs2[warp] = s2; }
    __syncthreads();
    s = 0.f; s2 = 0.f;
    #pragma unroll
    for (int w = 0; w < 8; w++) { s += rs1[w]; s2 += rs2[w]; }
    const float mu = s * (1.f / DM);
    const float var = s2 * (1.f / DM) - mu * mu;
    const float inv = rsqrtf(var + EPS);
    #pragma unroll
    for (int i = 0; i < 4; i++) {
        const int col = tid + i*256;
        out[row*DM + col] = (x[i] - mu) * inv * g[col] + beta[col];
    }
}

// ------------------------------- launch -----------------------------------
extern "C" void kernel_launch(void* const* d_in, const int* in_sizes, int n_in,
                              void* d_out, int out_size)
{
    const float* x    = (const float*)d_in[0];
    const float* enc  = (const float*)d_in[1];
    const float* lam  = (const float*)d_in[2];
    const float* pm   = (const float*)d_in[3];
    const float* wq1  = (const float*)d_in[4];  const float* bq1 = (const float*)d_in[5];
    const float* wk1  = (const float*)d_in[6];  const float* bk1 = (const float*)d_in[7];
    const float* wv1  = (const float*)d_in[8];  const float* bv1 = (const float*)d_in[9];
    const float* wo1  = (const float*)d_in[10]; const float* bo1 = (const float*)d_in[11];
    const float* wq2  = (const float*)d_in[12]; const float* bq2 = (const float*)d_in[13];
    const float* wk2  = (const float*)d_in[14]; const float* bk2 = (const float*)d_in[15];
    const float* wv2  = (const float*)d_in[16]; const float* bv2 = (const float*)d_in[17];
    const float* wo2  = (const float*)d_in[18]; const float* bo2 = (const float*)d_in[19];
    const float* wf1  = (const float*)d_in[20]; const float* bf1 = (const float*)d_in[21];
    const float* wf2  = (const float*)d_in[22]; const float* bf2 = (const float*)d_in[23];
    const float* ln2g = (const float*)d_in[24]; const float* ln2b = (const float*)d_in[25];
    const float* ln3g = (const float*)d_in[26]; const float* ln3b = (const float*)d_in[27];

    float* out3    = (float*)d_out;
    float* logits2 = (float*)d_out + (size_t)MT * DM;

    float *q, *k, *v, *ctx, *out1, *out2, *tmp, *ffn;
    bf16 *ab, *wt, *qs, *ks, *vs;
    cudaGetSymbolAddress((void**)&q,    g_q);
    cudaGetSymbolAddress((void**)&k,    g_k);
    cudaGetSymbolAddress((void**)&v,    g_v);
    cudaGetSymbolAddress((void**)&ctx,  g_ctx);
    cudaGetSymbolAddress((void**)&out1, g_out1);
    cudaGetSymbolAddress((void**)&out2, g_out2);
    cudaGetSymbolAddress((void**)&tmp,  g_tmp);
    cudaGetSymbolAddress((void**)&ffn,  g_ffn);
    cudaGetSymbolAddress((void**)&ab,   g_ab);
    cudaGetSymbolAddress((void**)&wt,   g_wt);
    cudaGetSymbolAddress((void**)&qs,   g_qs);
    cudaGetSymbolAddress((void**)&ks,   g_ks);
    cudaGetSymbolAddress((void**)&vs,   g_vs);

    const dim3 tWT(32, 8);
    const dim3 gWT_dd(DM/32, DM/32);
    const dim3 gWT_df(DFF/32, DM/32);
    const dim3 gWT_fd(DM/32, DFF/32);
    const dim3 gG_d(DM/128, MT/128);
    const dim3 gG_f(DFF/128, MT/128);
    const dim3 gFA(S/128, BH);
    const dim3 gSV(S/32, DP/32, BH);
    const int nSR_d = MT*DM/1024;
    const int nSR_f = (int)((size_t)MT*DFF/1024);
    const int faSmem = (128+64+64)*136*(int)sizeof(bf16);           // 69632
    cudaFuncSetAttribute(flash_attn<0>, cudaFuncAttributeMaxDynamicSharedMemorySize, faSmem);
    cudaFuncSetAttribute(flash_attn<1>, cudaFuncAttributeMaxDynamicSharedMemorySize, faSmem);

    // ===== MHA1 =====
    split_rows<<<nSR_d, 256>>>(x, ab, DM);
    split_wt<<<gWT_dd, tWT>>>(wq1, wt, DM, DM);
    hgemm_bias<<<gG_d, 256>>>(ab, wt, bq1, q, DM, DM, 0);
    split_wt<<<gWT_dd, tWT>>>(wk1, wt, DM, DM);
    hgemm_bias<<<gG_d, 256>>>(ab, wt, bk1, k, DM, DM, 0);
    split_wt<<<gWT_dd, tWT>>>(wv1, wt, DM, DM);
    hgemm_bias<<<gG_d, 256>>>(ab, wt, bv1, v, DM, DM, 0);
    split_qk<<<MT, 256>>>(q, qs);
    split_qk<<<MT, 256>>>(k, ks);
    split_v<<<gSV, tWT>>>(v, vs);
    flash_attn<0><<<gFA, 256, faSmem>>>(qs, ks, vs, lam, nullptr, ctx);
    split_rows<<<nSR_d, 256>>>(ctx, ab, DM);
    split_wt<<<gWT_dd, tWT>>>(wo1, wt, DM, DM);
    hgemm_bias<<<gG_d, 256>>>(ab, wt, bo1, out1, DM, DM, 0);

    // ===== MHA2 (raw logits2 -> d_out) =====
    split_rows<<<nSR_d, 256>>>(out1, ab, DM);
    split_wt<<<gWT_dd, tWT>>>(wq2, wt, DM, DM);
    hgemm_bias<<<gG_d, 256>>>(ab, wt, bq2, q, DM, DM, 0);
    split_rows<<<nSR_d, 256>>>(enc, ab, DM);
    split_wt<<<gWT_dd, tWT>>>(wk2, wt, DM, DM);
    hgemm_bias<<<gG_d, 256>>>(ab, wt, bk2, k, DM, DM, 0);
    split_wt<<<gWT_dd, tWT>>>(wv2, wt, DM, DM);
    hgemm_bias<<<gG_d, 256>>>(ab, wt, bv2, v, DM, DM, 0);
    split_qk<<<MT, 256>>>(q, qs);
    split_qk<<<MT, 256>>>(k, ks);
    split_v<<<gSV, tWT>>>(v, vs);
    flash_attn<1><<<gFA, 256, faSmem>>>(qs, ks, vs, pm, logits2, ctx);
    split_rows<<<nSR_d, 256>>>(ctx, ab, DM);
    split_wt<<<gWT_dd, tWT>>>(wo2, wt, DM, DM);
    hgemm_bias<<<gG_d, 256>>>(ab, wt, bo2, tmp, DM, DM, 0);
    add_ln_kernel<<<MT, 256>>>(tmp, out1, ln2g, ln2b, out2);

    // ===== FFN =====
    split_rows<<<nSR_d, 256>>>(out2, ab, DM);
    split_wt<<<gWT_df, tWT>>>(wf1, wt, DM, DFF);
    hgemm_bias<<<gG_f, 256>>>(ab, wt, bf1, ffn, DFF, DM, 1);
    split_rows<<<nSR_f, 256>>>(ffn, ab, DFF);
    split_wt<<<gWT_fd, tWT>>>(wf2, wt, DFF, DM);
    hgemm_bias<<<gG_d, 256>>>(ab, wt, bf2, tmp, DM, DFF, 0);
    add_ln_kernel<<<MT, 256>>>(tmp, out2, ln3g, ln3b, out3);
}